// round 1
// baseline (speedup 1.0000x reference)
#include <cuda_runtime.h>

#define NB 64
#define NT 512
#define NI 1024
#define NH 1024
#define NG 4096   // 4*H

// ---------------- static scratch ----------------
__device__ float g_Wih[NG * NI];                 // gate-interleaved Wih
__device__ float g_Whh[NG * NH];                 // gate-interleaved Whh
__device__ float g_bias[NG];                     // bih+bhh, interleaved
__device__ float g_Z[(size_t)NB * NT * NG];      // x-projection + bias (512 MB)
__device__ float g_Hst[2][128 * NH];             // double-buffered h (fwd rows 0..63, bwd 64..127)
__device__ float g_Cst[128 * NH];                // c state

__device__ __forceinline__ float tf32r(float x) {
    unsigned u;
    asm("cvt.rna.tf32.f32 %0, %1;" : "=r"(u) : "f"(x));
    return __uint_as_float(u);
}

__device__ __forceinline__ void mma8(float c[4], const unsigned a[4], const unsigned b[2]) {
    asm volatile(
        "mma.sync.aligned.m16n8k8.row.col.f32.tf32.tf32.f32 "
        "{%0,%1,%2,%3}, {%4,%5,%6,%7}, {%8,%9}, {%0,%1,%2,%3};\n"
        : "+f"(c[0]), "+f"(c[1]), "+f"(c[2]), "+f"(c[3])
        : "r"(a[0]), "r"(a[1]), "r"(a[2]), "r"(a[3]), "r"(b[0]), "r"(b[1]));
}

__device__ __forceinline__ float sigmf_(float x) { return 1.0f / (1.0f + __expf(-x)); }

// ---------------- prep kernels ----------------
// Permute weight rows so gate g of hidden unit j lands at row 4*j+g.
__global__ void prep_weights(const float* __restrict__ Wih, const float* __restrict__ Whh,
                             const float* __restrict__ bih, const float* __restrict__ bhh) {
    int idx = blockIdx.x * blockDim.x + threadIdx.x;   // < NG*1024
    int n = idx >> 10, k = idx & 1023;
    int j = n >> 2, g = n & 3;
    int src = (g * NH + j) * 1024 + k;
    g_Wih[idx] = Wih[src];
    g_Whh[idx] = Whh[src];
    if (k == 0) g_bias[n] = bih[g * NH + j] + bhh[g * NH + j];
}

__global__ void init_state(const float* __restrict__ h0f, const float* __restrict__ c0f,
                           const float* __restrict__ h0b, const float* __restrict__ c0b) {
    int idx = blockIdx.x * blockDim.x + threadIdx.x;   // < 128*1024
    int m = idx >> 10;
    float h, c;
    if (m < 64) { h = h0f[idx]; c = c0f[idx]; }
    else        { h = h0b[idx - 64 * NH]; c = c0b[idx - 64 * NH]; }
    g_Hst[0][idx] = h;
    g_Cst[idx] = c;
}

// ---------------- phase 1: Z = X @ Wih^T + bias ----------------
// BM=128, BN=128, BK=16, 256 threads, 8 warps (2 x 4), warp tile 64x32.
__global__ __launch_bounds__(256) void zproj_kernel(const float* __restrict__ X) {
    __shared__ float As[128 * 20];
    __shared__ float Bs2[128 * 20];
    int tid = threadIdx.x;
    int row0 = blockIdx.y * 128;
    int n0 = blockIdx.x * 128;
    const float* Ag = X + (size_t)row0 * NI;
    const float* Bg = g_Wih + (size_t)n0 * NI;

    int lr = tid >> 2;            // 0..63
    int lc = (tid & 3) * 4;
    int w = tid >> 5, lane = tid & 31, gid = lane >> 2, tig = lane & 3;
    int wm = (w >> 2) * 64, wn = (w & 3) * 32;

    float c[4][4][4];
#pragma unroll
    for (int mi = 0; mi < 4; mi++)
#pragma unroll
        for (int ni = 0; ni < 4; ni++)
#pragma unroll
            for (int q = 0; q < 4; q++) c[mi][ni][q] = 0.f;

    // prefetch iter 0
    float4 pa0 = *(const float4*)(Ag + (size_t)lr * NI + lc);
    float4 pa1 = *(const float4*)(Ag + (size_t)(lr + 64) * NI + lc);
    float4 pb0 = *(const float4*)(Bg + (size_t)lr * NI + lc);
    float4 pb1 = *(const float4*)(Bg + (size_t)(lr + 64) * NI + lc);

    for (int kk = 0; kk < NI; kk += 16) {
        *(float4*)&As[lr * 20 + lc] = make_float4(tf32r(pa0.x), tf32r(pa0.y), tf32r(pa0.z), tf32r(pa0.w));
        *(float4*)&As[(lr + 64) * 20 + lc] = make_float4(tf32r(pa1.x), tf32r(pa1.y), tf32r(pa1.z), tf32r(pa1.w));
        *(float4*)&Bs2[lr * 20 + lc] = make_float4(tf32r(pb0.x), tf32r(pb0.y), tf32r(pb0.z), tf32r(pb0.w));
        *(float4*)&Bs2[(lr + 64) * 20 + lc] = make_float4(tf32r(pb1.x), tf32r(pb1.y), tf32r(pb1.z), tf32r(pb1.w));
        __syncthreads();
        if (kk + 16 < NI) {      // prefetch next tile while mma runs
            pa0 = *(const float4*)(Ag + (size_t)lr * NI + kk + 16 + lc);
            pa1 = *(const float4*)(Ag + (size_t)(lr + 64) * NI + kk + 16 + lc);
            pb0 = *(const float4*)(Bg + (size_t)lr * NI + kk + 16 + lc);
            pb1 = *(const float4*)(Bg + (size_t)(lr + 64) * NI + kk + 16 + lc);
        }
#pragma unroll
        for (int k8 = 0; k8 < 16; k8 += 8) {
            unsigned a[4][4], b[4][2];
#pragma unroll
            for (int mi = 0; mi < 4; mi++) {
                int rb = wm + mi * 16 + gid;
                a[mi][0] = __float_as_uint(As[rb * 20 + k8 + tig]);
                a[mi][1] = __float_as_uint(As[(rb + 8) * 20 + k8 + tig]);
                a[mi][2] = __float_as_uint(As[rb * 20 + k8 + 4 + tig]);
                a[mi][3] = __float_as_uint(As[(rb + 8) * 20 + k8 + 4 + tig]);
            }
#pragma unroll
            for (int ni = 0; ni < 4; ni++) {
                int nb = wn + ni * 8 + gid;
                b[ni][0] = __float_as_uint(Bs2[nb * 20 + k8 + tig]);
                b[ni][1] = __float_as_uint(Bs2[nb * 20 + k8 + 4 + tig]);
            }
#pragma unroll
            for (int mi = 0; mi < 4; mi++)
#pragma unroll
                for (int ni = 0; ni < 4; ni++) mma8(c[mi][ni], a[mi], b[ni]);
        }
        __syncthreads();
    }

#pragma unroll
    for (int mi = 0; mi < 4; mi++)
#pragma unroll
        for (int ni = 0; ni < 4; ni++) {
            int r = row0 + wm + mi * 16 + gid;
            int col = n0 + wn + ni * 8 + tig * 2;
            float b0 = g_bias[col], b1 = g_bias[col + 1];
            size_t o = (size_t)r * NG + col;
            g_Z[o] = c[mi][ni][0] + b0;
            g_Z[o + 1] = c[mi][ni][1] + b1;
            o += (size_t)8 * NG;
            g_Z[o] = c[mi][ni][2] + b0;
            g_Z[o + 1] = c[mi][ni][3] + b1;
        }
}

// ---------------- phase 2: one recurrent step ----------------
// gates = Hcat @ Whh^T (+ Z) for 128 rows (64 fwd + 64 bwd), fused LSTM epilogue.
// BM=64, BN=64, BK=16, 256 threads, 8 warps (2 x 4), warp tile 32x16. grid (64, 2).
__global__ __launch_bounds__(256) void step_kernel(float* __restrict__ out, int t) {
    __shared__ float sm[64 * 68];   // GEMM tiles (2 x 64x20) then epilogue 64x68
    float* As = sm;
    float* Bs2 = sm + 64 * 20;
    int tid = threadIdx.x;
    int mrow0 = blockIdx.y * 64;    // 0 = forward batch, 64 = backward batch
    int n0 = blockIdx.x * 64;
    const float* Ag = g_Hst[t & 1] + (size_t)mrow0 * NH;
    const float* Bg = g_Whh + (size_t)n0 * NH;

    int lr = tid >> 2;              // 0..63
    int lc = (tid & 3) * 4;
    int w = tid >> 5, lane = tid & 31, gid = lane >> 2, tig = lane & 3;
    int wm = (w >> 2) * 32, wn = (w & 3) * 16;

    float c[2][2][4];
#pragma unroll
    for (int mi = 0; mi < 2; mi++)
#pragma unroll
        for (int ni = 0; ni < 2; ni++)
#pragma unroll
            for (int q = 0; q < 4; q++) c[mi][ni][q] = 0.f;

    float4 pa = *(const float4*)(Ag + (size_t)lr * NH + lc);
    float4 pb = *(const float4*)(Bg + (size_t)lr * NH + lc);

    for (int kk = 0; kk < NH; kk += 16) {
        *(float4*)&As[lr * 20 + lc] = make_float4(tf32r(pa.x), tf32r(pa.y), tf32r(pa.z), tf32r(pa.w));
        *(float4*)&Bs2[lr * 20 + lc] = make_float4(tf32r(pb.x), tf32r(pb.y), tf32r(pb.z), tf32r(pb.w));
        __syncthreads();
        if (kk + 16 < NH) {
            pa = *(const float4*)(Ag + (size_t)lr * NH + kk + 16 + lc);
            pb = *(const float4*)(Bg + (size_t)lr * NH + kk + 16 + lc);
        }
#pragma unroll
        for (int k8 = 0; k8 < 16; k8 += 8) {
            unsigned a[2][4], b[2][2];
#pragma unroll
            for (int mi = 0; mi < 2; mi++) {
                int rb = wm + mi * 16 + gid;
                a[mi][0] = __float_as_uint(As[rb * 20 + k8 + tig]);
                a[mi][1] = __float_as_uint(As[(rb + 8) * 20 + k8 + tig]);
                a[mi][2] = __float_as_uint(As[rb * 20 + k8 + 4 + tig]);
                a[mi][3] = __float_as_uint(As[(rb + 8) * 20 + k8 + 4 + tig]);
            }
#pragma unroll
            for (int ni = 0; ni < 2; ni++) {
                int nb = wn + ni * 8 + gid;
                b[ni][0] = __float_as_uint(Bs2[nb * 20 + k8 + tig]);
                b[ni][1] = __float_as_uint(Bs2[nb * 20 + k8 + 4 + tig]);
            }
#pragma unroll
            for (int mi = 0; mi < 2; mi++)
#pragma unroll
                for (int ni = 0; ni < 2; ni++) mma8(c[mi][ni], a[mi], b[ni]);
        }
        __syncthreads();
    }

    // dump accumulators to smem (raw gate pre-activations, minus Z)
    float* gsm = sm;   // 64 rows x stride 68
#pragma unroll
    for (int mi = 0; mi < 2; mi++)
#pragma unroll
        for (int ni = 0; ni < 2; ni++) {
            int r = wm + mi * 16 + gid;
            int cl = wn + ni * 8 + tig * 2;
            gsm[r * 68 + cl] = c[mi][ni][0];
            gsm[r * 68 + cl + 1] = c[mi][ni][1];
            gsm[(r + 8) * 68 + cl] = c[mi][ni][2];
            gsm[(r + 8) * 68 + cl + 1] = c[mi][ni][3];
        }
    __syncthreads();

    // fused LSTM pointwise: this BN=64 tile holds complete i,f,g,o for 16 units
    for (int idx = tid; idx < 64 * 16; idx += 256) {
        int mr = idx >> 4, jl = idx & 15;
        int m = mrow0 + mr;
        size_t zb = (m < 64) ? ((size_t)m * NT + t) * NG
                             : ((size_t)(m - 64) * NT + (NT - 1 - t)) * NG;
        float4 z = *(const float4*)&g_Z[zb + n0 + jl * 4];
        float iv = sigmf_(gsm[mr * 68 + jl * 4 + 0] + z.x);
        float fv = sigmf_(gsm[mr * 68 + jl * 4 + 1] + z.y);
        float gv = tanhf(gsm[mr * 68 + jl * 4 + 2] + z.z);
        float ov = sigmf_(gsm[mr * 68 + jl * 4 + 3] + z.w);
        int j = (n0 >> 2) + jl;
        int hc = m * NH + j;
        float cv = fv * g_Cst[hc] + iv * gv;
        g_Cst[hc] = cv;
        float h = ov * tanhf(cv);
        g_Hst[(t + 1) & 1][hc] = h;
        if (m < 64) {
            // output[:, :, 0:H] = out_f ; output[:, :, H:2H] = out_f batch-reversed
            out[((size_t)m * NT + t) * 2048 + j] = h;
            out[((size_t)(63 - m) * NT + t) * 2048 + 1024 + j] = h;
        }
    }
}

// ---------------- final h_i / c_i ----------------
__global__ void final_kernel(float* __restrict__ out) {
    int idx = blockIdx.x * blockDim.x + threadIdx.x;   // < 128*1024
    int m = idx >> 10, j = idx & 1023;
    int b = m & 63, dir = m >> 6;
    size_t base = (size_t)NB * NT * 2048;
    out[base + (size_t)b * 2048 + dir * 1024 + j] = g_Hst[0][idx];           // h_i (T even -> buf 0)
    out[base + 131072 + (size_t)b * 2048 + dir * 1024 + j] = g_Cst[idx];     // c_i
}

extern "C" void kernel_launch(void* const* d_in, const int* in_sizes, int n_in,
                              void* d_out, int out_size) {
    const float* x     = (const float*)d_in[0];
    const float* Wih_f = (const float*)d_in[1];
    const float* Whh_f = (const float*)d_in[2];
    const float* bih_f = (const float*)d_in[3];
    const float* bhh_f = (const float*)d_in[4];
    // d_in[5..8] (_b weights) are unused by the reference computation.
    const float* h0f   = (const float*)d_in[9];
    const float* c0f   = (const float*)d_in[10];
    const float* h0b   = (const float*)d_in[11];
    const float* c0b   = (const float*)d_in[12];
    float* out = (float*)d_out;

    prep_weights<<<(NG * NI) / 256, 256>>>(Wih_f, Whh_f, bih_f, bhh_f);
    init_state<<<(128 * NH) / 256, 256>>>(h0f, c0f, h0b, c0b);

    dim3 zg(NG / 128, (NB * NT) / 128);   // (32, 256)
    zproj_kernel<<<zg, 256>>>(x);

    for (int t = 0; t < NT; t++) {
        step_kernel<<<dim3(NG / 64, 2), 256>>>(out, t);
    }
    final_kernel<<<(128 * NH) / 256, 256>>>(out);
}

// round 5
// speedup vs baseline: 1.8253x; 1.8253x over previous
#include <cuda_runtime.h>

#define NB 64
#define NT 512
#define NI 1024
#define NH 1024
#define NG 4096   // 4*H
#define NBLK 128  // persistent blocks
#define WS 1028   // Whh smem row stride (floats): 1028 % 32 == 4 -> conflict-free frags
#define EPS 132   // epilogue smem row stride

// ---------------- static scratch ----------------
__device__ float g_Wih[NG * NI];                 // gate-interleaved Wih
__device__ float g_Whh[NG * NH];                 // gate-interleaved Whh
__device__ float g_bias[NG];                     // bih+bhh, interleaved
__device__ float g_Z[(size_t)NB * NT * NG];      // x-projection + bias (512 MB)
__device__ float g_Hfrag[2 * 128 * 128 * 8];     // [buf][k/8][batch m][pair-perm k%8]
__device__ unsigned g_barcnt;
__device__ volatile unsigned g_barphase;

__device__ __forceinline__ float tf32r(float x) {
    unsigned u;
    asm("cvt.rna.tf32.f32 %0, %1;" : "=r"(u) : "f"(x));
    return __uint_as_float(u);
}
__device__ __forceinline__ unsigned fu(float x) { return __float_as_uint(x); }

__device__ __forceinline__ void mma8(float c[4], const unsigned a[4], const unsigned b[2]) {
    asm volatile(
        "mma.sync.aligned.m16n8k8.row.col.f32.tf32.tf32.f32 "
        "{%0,%1,%2,%3}, {%4,%5,%6,%7}, {%8,%9}, {%0,%1,%2,%3};\n"
        : "+f"(c[0]), "+f"(c[1]), "+f"(c[2]), "+f"(c[3])
        : "r"(a[0]), "r"(a[1]), "r"(a[2]), "r"(a[3]), "r"(b[0]), "r"(b[1]));
}

__device__ __forceinline__ float sigmf_(float x) { return 1.0f / (1.0f + __expf(-x)); }

// ---------------- prep kernels ----------------
__global__ void prep_weights(const float* __restrict__ Wih, const float* __restrict__ Whh,
                             const float* __restrict__ bih, const float* __restrict__ bhh) {
    int idx = blockIdx.x * blockDim.x + threadIdx.x;   // < NG*1024
    int n = idx >> 10, k = idx & 1023;
    int j = n >> 2, g = n & 3;
    int src = (g * NH + j) * 1024 + k;
    g_Wih[idx] = Wih[src];
    g_Whh[idx] = Whh[src];
    if (k == 0) g_bias[n] = bih[g * NH + j] + bhh[g * NH + j];
}

// h0 -> H_frag[0] in fragment-native layout, tf32-rounded
__global__ void init_state(const float* __restrict__ h0f, const float* __restrict__ h0b) {
    int idx = blockIdx.x * blockDim.x + threadIdx.x;   // < 128*1024
    int m = idx >> 10, j = idx & 1023;
    float h = (m < 64) ? h0f[m * NH + j] : h0b[(m - 64) * NH + j];
    int p = ((j & 3) << 1) | ((j >> 2) & 1);
    g_Hfrag[((size_t)(j >> 3) * 128 + m) * 8 + p] = tf32r(h);
}

__global__ void reset_bar() { g_barcnt = 0; g_barphase = 0; }

// ---------------- phase 1: Z = X @ Wih^T + bias ----------------
__global__ __launch_bounds__(256) void zproj_kernel(const float* __restrict__ X) {
    __shared__ float As[128 * 20];
    __shared__ float Bs2[128 * 20];
    int tid = threadIdx.x;
    int row0 = blockIdx.y * 128;
    int n0 = blockIdx.x * 128;
    const float* Ag = X + (size_t)row0 * NI;
    const float* Bg = g_Wih + (size_t)n0 * NI;

    int lr = tid >> 2;
    int lc = (tid & 3) * 4;
    int w = tid >> 5, lane = tid & 31, gid = lane >> 2, tig = lane & 3;
    int wm = (w >> 2) * 64, wn = (w & 3) * 32;

    float c[4][4][4];
#pragma unroll
    for (int mi = 0; mi < 4; mi++)
#pragma unroll
        for (int ni = 0; ni < 4; ni++)
#pragma unroll
            for (int q = 0; q < 4; q++) c[mi][ni][q] = 0.f;

    float4 pa0 = *(const float4*)(Ag + (size_t)lr * NI + lc);
    float4 pa1 = *(const float4*)(Ag + (size_t)(lr + 64) * NI + lc);
    float4 pb0 = *(const float4*)(Bg + (size_t)lr * NI + lc);
    float4 pb1 = *(const float4*)(Bg + (size_t)(lr + 64) * NI + lc);

    for (int kk = 0; kk < NI; kk += 16) {
        *(float4*)&As[lr * 20 + lc] = make_float4(tf32r(pa0.x), tf32r(pa0.y), tf32r(pa0.z), tf32r(pa0.w));
        *(float4*)&As[(lr + 64) * 20 + lc] = make_float4(tf32r(pa1.x), tf32r(pa1.y), tf32r(pa1.z), tf32r(pa1.w));
        *(float4*)&Bs2[lr * 20 + lc] = make_float4(tf32r(pb0.x), tf32r(pb0.y), tf32r(pb0.z), tf32r(pb0.w));
        *(float4*)&Bs2[(lr + 64) * 20 + lc] = make_float4(tf32r(pb1.x), tf32r(pb1.y), tf32r(pb1.z), tf32r(pb1.w));
        __syncthreads();
        if (kk + 16 < NI) {
            pa0 = *(const float4*)(Ag + (size_t)lr * NI + kk + 16 + lc);
            pa1 = *(const float4*)(Ag + (size_t)(lr + 64) * NI + kk + 16 + lc);
            pb0 = *(const float4*)(Bg + (size_t)lr * NI + kk + 16 + lc);
            pb1 = *(const float4*)(Bg + (size_t)(lr + 64) * NI + kk + 16 + lc);
        }
#pragma unroll
        for (int k8 = 0; k8 < 16; k8 += 8) {
            unsigned a[4][4], b[4][2];
#pragma unroll
            for (int mi = 0; mi < 4; mi++) {
                int rb = wm + mi * 16 + gid;
                a[mi][0] = fu(As[rb * 20 + k8 + tig]);
                a[mi][1] = fu(As[(rb + 8) * 20 + k8 + tig]);
                a[mi][2] = fu(As[rb * 20 + k8 + 4 + tig]);
                a[mi][3] = fu(As[(rb + 8) * 20 + k8 + 4 + tig]);
            }
#pragma unroll
            for (int ni = 0; ni < 4; ni++) {
                int nb = wn + ni * 8 + gid;
                b[ni][0] = fu(Bs2[nb * 20 + k8 + tig]);
                b[ni][1] = fu(Bs2[nb * 20 + k8 + 4 + tig]);
            }
#pragma unroll
            for (int mi = 0; mi < 4; mi++)
#pragma unroll
                for (int ni = 0; ni < 4; ni++) mma8(c[mi][ni], a[mi], b[ni]);
        }
        __syncthreads();
    }

#pragma unroll
    for (int mi = 0; mi < 4; mi++)
#pragma unroll
        for (int ni = 0; ni < 4; ni++) {
            int r = row0 + wm + mi * 16 + gid;
            int col = n0 + wn + ni * 8 + tig * 2;
            float b0 = g_bias[col], b1 = g_bias[col + 1];
            size_t o = (size_t)r * NG + col;
            g_Z[o] = c[mi][ni][0] + b0;
            g_Z[o + 1] = c[mi][ni][1] + b1;
            o += (size_t)8 * NG;
            g_Z[o] = c[mi][ni][2] + b0;
            g_Z[o + 1] = c[mi][ni][3] + b1;
        }
}

// ---------------- grid barrier ----------------
__device__ __forceinline__ void grid_bar(unsigned target) {
    __syncthreads();
    if (threadIdx.x == 0) {
        __threadfence();
        unsigned old = atomicAdd(&g_barcnt, 1u);
        if (old == NBLK - 1) {
            g_barcnt = 0;
            __threadfence();
            g_barphase = target;
        } else {
            while (g_barphase < target) { __nanosleep(40); }
        }
        __threadfence();
    }
    __syncthreads();
}

// ---------------- persistent recurrent kernel ----------------
// Block b: gate cols [32b,32b+32) (hidden units 8b..8b+8). Whh slice in SMEM.
// gates^T(gatecol, batch) = Whh_s @ H^T; H fragments straight from L2 (.cg).
// Warp w: batch group [16w, 16w+16), full 32 gate cols, full K=1024.
__global__ __launch_bounds__(256, 1) void lstm_persistent(float* __restrict__ out,
                                                          const float* __restrict__ c0f,
                                                          const float* __restrict__ c0b) {
    extern __shared__ float smdyn[];
    float* Wsh = smdyn;              // 32 x WS
    float* gep = smdyn + 32 * WS;    // 32 x EPS

    const int b = blockIdx.x, tid = threadIdx.x;
    const int w = tid >> 5, gid = (tid & 31) >> 2, tig = tid & 3;

    // load + tf32-round Whh slice
    for (int i = tid; i < 32 * 1024; i += 256) {
        int r = i >> 10, k = i & 1023;
        Wsh[r * WS + k] = tf32r(g_Whh[(size_t)(b * 32 + r) * 1024 + k]);
    }

    // pointwise-thread mapping: item it -> (m = (it*256+tid)>>3, u = (it*256+tid)&7)
    float Creg[4];
#pragma unroll
    for (int it = 0; it < 4; it++) {
        int idx = it * 256 + tid, m = idx >> 3, u = idx & 7, j = b * 8 + u;
        Creg[it] = (m < 64) ? c0f[m * NH + j] : c0b[(m - 64) * NH + j];
    }

    // per-lane constant offsets
    const float* Wl = Wsh + gid * WS + tig;                    // A frag base (mt=0)
    const size_t bo0 = (size_t)(w * 16 + gid) * 8 + tig * 2;   // B frag ntile 0
    const size_t bo1 = bo0 + 64;                               // B frag ntile 1
    const size_t OB = (size_t)NB * NT * 2048;

    __syncthreads();

    for (int t = 0; t < NT; t++) {
        const float* Hb = g_Hfrag + (size_t)(t & 1) * 131072;

        // prefetch Z for this step (DRAM) — consumed only in the epilogue,
        // so the latency hides under the K-loop MMAs.
        float4 zreg[4];
#pragma unroll
        for (int it = 0; it < 4; it++) {
            int idx = it * 256 + tid, m = idx >> 3, u = idx & 7;
            size_t zoff = (m < 64) ? ((size_t)m * NT + t) * NG
                                   : ((size_t)(m - 64) * NT + (NT - 1 - t)) * NG;
            zreg[it] = *(const float4*)&g_Z[zoff + b * 32 + u * 4];
        }

        float acc[2][2][4];
#pragma unroll
        for (int mt = 0; mt < 2; mt++)
#pragma unroll
            for (int nt = 0; nt < 2; nt++)
#pragma unroll
                for (int q = 0; q < 4; q++) acc[mt][nt][q] = 0.f;

#pragma unroll 8
        for (int ks = 0; ks < 128; ks++) {
            float2 f0 = __ldcg((const float2*)(Hb + (size_t)ks * 1024 + bo0));
            float2 f1 = __ldcg((const float2*)(Hb + (size_t)ks * 1024 + bo1));
            unsigned bb0[2] = {fu(f0.x), fu(f0.y)};
            unsigned bb1[2] = {fu(f1.x), fu(f1.y)};
#pragma unroll
            for (int mt = 0; mt < 2; mt++) {
                const float* Ap = Wl + mt * 16 * WS + ks * 8;
                unsigned a[4];
                a[0] = fu(Ap[0]);
                a[1] = fu(Ap[8 * WS]);
                a[2] = fu(Ap[4]);
                a[3] = fu(Ap[8 * WS + 4]);
                mma8(acc[mt][0], a, bb0);
                mma8(acc[mt][1], a, bb1);
            }
        }

        __syncthreads();   // previous pointwise reads of gep are done
        // accum -> smem: gep[gatecol][batch]
#pragma unroll
        for (int mt = 0; mt < 2; mt++)
#pragma unroll
            for (int nt = 0; nt < 2; nt++) {
                int mr = mt * 16 + gid;
                int nc = w * 16 + nt * 8 + 2 * tig;
                gep[mr * EPS + nc] = acc[mt][nt][0];
                gep[mr * EPS + nc + 1] = acc[mt][nt][1];
                gep[(mr + 8) * EPS + nc] = acc[mt][nt][2];
                gep[(mr + 8) * EPS + nc + 1] = acc[mt][nt][3];
            }
        __syncthreads();

        float* Hn = g_Hfrag + (size_t)((t + 1) & 1) * 131072 + (size_t)b * 1024;
#pragma unroll
        for (int it = 0; it < 4; it++) {
            int idx = it * 256 + tid, m = idx >> 3, u = idx & 7, j = b * 8 + u;
            float4 z = zreg[it];
            float iv = sigmf_(gep[(4 * u + 0) * EPS + m] + z.x);
            float fv = sigmf_(gep[(4 * u + 1) * EPS + m] + z.y);
            float gv = tanhf(gep[(4 * u + 2) * EPS + m] + z.z);
            float ov = sigmf_(gep[(4 * u + 3) * EPS + m] + z.w);
            float cv = fv * Creg[it] + iv * gv;
            Creg[it] = cv;
            float h = ov * tanhf(cv);
            int p = ((u & 3) << 1) | (u >> 2);
            Hn[m * 8 + p] = tf32r(h);
            if (m < 64) {
                out[((size_t)m * NT + t) * 2048 + j] = h;
                out[((size_t)(63 - m) * NT + t) * 2048 + 1024 + j] = h;
                if (t == NT - 1) out[OB + (size_t)m * 2048 + j] = h;
            } else if (t == NT - 1) {
                out[OB + (size_t)(m - 64) * 2048 + 1024 + j] = h;
            }
        }

        grid_bar((unsigned)(t + 1));
    }

    // c_i from registers
#pragma unroll
    for (int it = 0; it < 4; it++) {
        int idx = it * 256 + tid, m = idx >> 3, u = idx & 7, j = b * 8 + u;
        size_t o = OB + 131072 + ((m < 64) ? ((size_t)m * 2048 + j)
                                           : ((size_t)(m - 64) * 2048 + 1024 + j));
        out[o] = Creg[it];
    }
}

extern "C" void kernel_launch(void* const* d_in, const int* in_sizes, int n_in,
                              void* d_out, int out_size) {
    const float* x     = (const float*)d_in[0];
    const float* Wih_f = (const float*)d_in[1];
    const float* Whh_f = (const float*)d_in[2];
    const float* bih_f = (const float*)d_in[3];
    const float* bhh_f = (const float*)d_in[4];
    // d_in[5..8] (_b weights) are unused by the reference computation.
    const float* h0f   = (const float*)d_in[9];
    const float* c0f   = (const float*)d_in[10];
    const float* h0b   = (const float*)d_in[11];
    const float* c0b   = (const float*)d_in[12];
    float* out = (float*)d_out;

    const int smem_bytes = (32 * WS + 32 * EPS) * 4;   // 148480
    cudaFuncSetAttribute(lstm_persistent, cudaFuncAttributeMaxDynamicSharedMemorySize, smem_bytes);

    prep_weights<<<(NG * NI) / 256, 256>>>(Wih_f, Whh_f, bih_f, bhh_f);
    init_state<<<(128 * NH) / 256, 256>>>(h0f, h0b);

    dim3 zg(NG / 128, (NB * NT) / 128);   // (32, 256)
    zproj_kernel<<<zg, 256>>>(x);

    reset_bar<<<1, 1>>>();
    lstm_persistent<<<NBLK, 256, smem_bytes>>>(out, c0f, c0b);
}